// round 13
// baseline (speedup 1.0000x reference)
#include <cuda_runtime.h>
#include <cuda_fp16.h>
#include <math.h>

// Problem constants (fixed by the dataset)
#define NN     10000         // nodes
#define EE     320000        // edges (before self loops)
#define ET     (EE + NN)     // edges incl. self loops
#define HH     4             // heads
#define CC     128           // channels per head
#define HC     (HH * CC)     // 512
#define EB     4             // edges per thread in fill
#define CAPDEG 192           // per-node bucket capacity (Poisson(33); P(>80)~1e-12)

// ---------------- scratch (static device globals; no allocs allowed) ----------
__device__ __align__(16) __half2 g_h2[NN * HC / 2];   // fp16 feats [N, H*C] (10.2 MB)
__device__ __align__(16) __half  g_wt[HC * CC];       // fp16 W^T [512,128] (128 KB)
__device__ float g_asrc[NN * HH];        // per-node src attention logits [N,4]
__device__ float g_adst[NN * HH];        // per-node dst attention logits [N,4]
__device__ int   g_cursor[NN];           // bucket cursors (zero at entry; agg restores)
__device__ int   g_src2[NN * CAPDEG];    // bucketed edge sources [node][CAPDEG]

// ---------------- inline edge-dtype detection ---------------------------------
__device__ __forceinline__ int detect_is64(const int* __restrict__ e32) {
    int any = 0;
#pragma unroll
    for (int k = 0; k < 8; k++) any |= e32[2 * k + 1];
    return any == 0;
}
__device__ __forceinline__ int edge_at(const void* edge, long long idx, int is64) {
    if (is64) return (int)((const long long*)edge)[idx];
    return ((const int*)edge)[idx];
}
__device__ __forceinline__ unsigned smem_u32(const void* p) {
    return (unsigned)__cvta_generic_to_shared(p);
}

// ---------------- cvt: W -> W^T fp16 (tiny) ------------------------------------
__global__ void cvtw_kernel(const float* __restrict__ W) {
    int j = blockIdx.x * blockDim.x + threadIdx.x;
    if (j < HC * CC) {                 // W^T[n][k] = W[k][n]
        int n = j >> 7, k = j & 127;
        g_wt[j] = __float2half(W[k * HC + n]);
    }
}

// ---------------- HMMA GEMM + fused attention dots -----------------------------
// h[N,512] = x[N,128] @ W[128,512] in fp16 tensor cores, fp32 accumulate.
// Block: 128 rows x 128 cols (one head). 8 warps as 4x2, each warp 32x64.
// x converted fp32->fp16 inline during A-tile staging.
__global__ void __launch_bounds__(256) gemm_kernel(
        const float* __restrict__ x,
        const float* __restrict__ att_src, const float* __restrict__ att_dst) {
    __shared__ __half sA[128][72];     // x tile, pad-72 (conflict-free ldmatrix)
    __shared__ __half sB[128][72];     // W^T tile (rows = n, cols = k)
    __shared__ float  sdot[128][4];    // [row][vs_wn0, vs_wn1, vd_wn0, vd_wn1]

    const int tid  = threadIdx.x;
    const int wid  = tid >> 5;
    const int lane = tid & 31;
    const int wm   = wid & 3;          // row group: wm*32
    const int wn   = wid >> 2;         // col group: wn*64
    const int row0 = blockIdx.x * 128;
    const int head = blockIdx.y;

    float c[2][8][4];
#pragma unroll
    for (int mt = 0; mt < 2; mt++)
#pragma unroll
        for (int nt = 0; nt < 8; nt++)
#pragma unroll
            for (int q = 0; q < 4; q++) c[mt][nt][q] = 0.f;

    for (int ks = 0; ks < CC; ks += 64) {
        // load A: 128 rows x 64 k halfs; fp32 source converted inline
#pragma unroll
        for (int cc = 0; cc < 4; cc++) {
            int ch = tid + cc * 256;               // 0..1023 chunks of 8 halfs
            int r = ch >> 3, k8 = ch & 7;
            int rg = row0 + r;
            union alignas(16) { __half2 h2[4]; uint4 u; } v;
            if (rg < NN) {
                const float4 f0 = *(const float4*)&x[rg * CC + ks + k8 * 8];
                const float4 f1 = *(const float4*)&x[rg * CC + ks + k8 * 8 + 4];
                v.h2[0] = __floats2half2_rn(f0.x, f0.y);
                v.h2[1] = __floats2half2_rn(f0.z, f0.w);
                v.h2[2] = __floats2half2_rn(f1.x, f1.y);
                v.h2[3] = __floats2half2_rn(f1.z, f1.w);
            } else {
                v.u = make_uint4(0, 0, 0, 0);
            }
            *(uint4*)&sA[r][k8 * 8] = v.u;
        }
        // load B: 128 n-rows x 64 k halfs
#pragma unroll
        for (int cc = 0; cc < 4; cc++) {
            int ch = tid + cc * 256;
            int r = ch >> 3, k8 = ch & 7;
            uint4 v = *(const uint4*)&g_wt[(head * 128 + r) * CC + ks + k8 * 8];
            *(uint4*)&sB[r][k8 * 8] = v;
        }
        __syncthreads();

#pragma unroll
        for (int kk = 0; kk < 4; kk++) {
            const int k = kk * 16;
            unsigned a[2][4], b[8][2];
#pragma unroll
            for (int mt = 0; mt < 2; mt++) {
                int am = wm * 32 + mt * 16;
                unsigned addr = smem_u32(&sA[am + (lane & 15)][k + ((lane >> 4) << 3)]);
                asm volatile("ldmatrix.sync.aligned.m8n8.x4.shared.b16 {%0,%1,%2,%3}, [%4];"
                             : "=r"(a[mt][0]), "=r"(a[mt][1]), "=r"(a[mt][2]), "=r"(a[mt][3])
                             : "r"(addr));
            }
#pragma unroll
            for (int nt = 0; nt < 8; nt++) {
                int bn = wn * 64 + nt * 8;
                int l = lane & 15;
                unsigned addr = smem_u32(&sB[bn + (l & 7)][k + ((l >> 3) << 3)]);
                asm volatile("ldmatrix.sync.aligned.m8n8.x2.shared.b16 {%0,%1}, [%2];"
                             : "=r"(b[nt][0]), "=r"(b[nt][1]) : "r"(addr));
            }
#pragma unroll
            for (int mt = 0; mt < 2; mt++)
#pragma unroll
                for (int nt = 0; nt < 8; nt++) {
                    asm volatile(
                        "mma.sync.aligned.m16n8k16.row.col.f32.f16.f16.f32 "
                        "{%0,%1,%2,%3}, {%4,%5,%6,%7}, {%8,%9}, {%0,%1,%2,%3};"
                        : "+f"(c[mt][nt][0]), "+f"(c[mt][nt][1]),
                          "+f"(c[mt][nt][2]), "+f"(c[mt][nt][3])
                        : "r"(a[mt][0]), "r"(a[mt][1]), "r"(a[mt][2]), "r"(a[mt][3]),
                          "r"(b[nt][0]), "r"(b[nt][1]));
                }
        }
        __syncthreads();
    }

    // epilogue: h (fp16) stores + attention dot partials
    const int q = lane & 3;            // col pair selector
    const int rq = lane >> 2;          // row within m8
    float vs1[2] = {0.f, 0.f}, vs2[2] = {0.f, 0.f};
    float vd1[2] = {0.f, 0.f}, vd2[2] = {0.f, 0.f};
#pragma unroll
    for (int nt = 0; nt < 8; nt++) {
        int col = wn * 64 + nt * 8 + q * 2;        // within-head col
        float as0 = att_src[head * CC + col], as1 = att_src[head * CC + col + 1];
        float ad0 = att_dst[head * CC + col], ad1 = att_dst[head * CC + col + 1];
#pragma unroll
        for (int mt = 0; mt < 2; mt++) {
            int r1 = row0 + wm * 32 + mt * 16 + rq;
            int r2 = r1 + 8;
            if (r1 < NN)
                g_h2[(size_t)r1 * (HC / 2) + (head * CC + col) / 2] =
                    __floats2half2_rn(c[mt][nt][0], c[mt][nt][1]);
            if (r2 < NN)
                g_h2[(size_t)r2 * (HC / 2) + (head * CC + col) / 2] =
                    __floats2half2_rn(c[mt][nt][2], c[mt][nt][3]);
            vs1[mt] += c[mt][nt][0] * as0 + c[mt][nt][1] * as1;
            vs2[mt] += c[mt][nt][2] * as0 + c[mt][nt][3] * as1;
            vd1[mt] += c[mt][nt][0] * ad0 + c[mt][nt][1] * ad1;
            vd2[mt] += c[mt][nt][2] * ad0 + c[mt][nt][3] * ad1;
        }
    }
#pragma unroll
    for (int mt = 0; mt < 2; mt++) {
#pragma unroll
        for (int off = 1; off <= 2; off <<= 1) {
            vs1[mt] += __shfl_xor_sync(0xFFFFFFFFu, vs1[mt], off);
            vs2[mt] += __shfl_xor_sync(0xFFFFFFFFu, vs2[mt], off);
            vd1[mt] += __shfl_xor_sync(0xFFFFFFFFu, vd1[mt], off);
            vd2[mt] += __shfl_xor_sync(0xFFFFFFFFu, vd2[mt], off);
        }
        if (q == 0) {
            int rl = wm * 32 + mt * 16 + rq;
            sdot[rl][wn] = vs1[mt];     sdot[rl][2 + wn] = vd1[mt];
            sdot[rl + 8][wn] = vs2[mt]; sdot[rl + 8][2 + wn] = vd2[mt];
        }
    }
    __syncthreads();
    if (tid < 128) {
        int rg = row0 + tid;
        if (rg < NN) {
            g_asrc[rg * HH + head] = sdot[tid][0] + sdot[tid][1];
            g_adst[rg * HH + head] = sdot[tid][2] + sdot[tid][3];
        }
    }
}

// ---------------- bucket fill: edges + self loops ------------------------------
__global__ void fill_kernel(const void* __restrict__ edge) {
    int e0 = (blockIdx.x * blockDim.x + threadIdx.x) * EB;
    if (e0 >= ET) return;
    int is64 = detect_is64((const int*)edge);
    int s[EB], d[EB];
#pragma unroll
    for (int q = 0; q < EB; q++) {
        int e = e0 + q;
        s[q] = -1; d[q] = -1;
        if (e < ET) {
            if (e < EE) {
                s[q] = edge_at(edge, (long long)e, is64);
                d[q] = edge_at(edge, (long long)EE + e, is64);
            } else {
                s[q] = e - EE; d[q] = e - EE;
            }
        }
    }
#pragma unroll
    for (int q = 0; q < EB; q++) {
        if ((unsigned)d[q] >= NN || (unsigned)s[q] >= NN) continue;
        int pos = atomicAdd(&g_cursor[d[q]], 1);
        if (pos < CAPDEG) g_src2[d[q] * CAPDEG + pos] = s[q];
    }
}

// ---------------- fused softmax + gather aggregation ---------------------------
// Block = 128 threads = one node.
// Softmax: warp w = head w (own slice).
// Gather: thread (half = tid>>6, sub = tid&63) owns 8 channels [sub*8, sub*8+8)
// via one uint4 fp16 load; halves take alternating edges; partials combined
// through smem. Row offsets precomputed. deg <= CAPDEG => single chunk.
__global__ void __launch_bounds__(128) agg_kernel(
        const float* __restrict__ bias, float* __restrict__ out) {
    const int i     = blockIdx.x;
    const int tid   = threadIdx.x;
    const int wid   = tid >> 5;        // softmax head
    const int lane  = tid & 31;
    const int half  = tid >> 6;        // edge parity
    const int sub   = tid & 63;        // channel group
    const int chead = sub >> 4;        // head owning these channels
    const int deg   = min(g_cursor[i], CAPDEG);

    __shared__ float s_e[HH][CAPDEG + 1];   // +1 pad: heads land in distinct banks
    __shared__ int   s_off[CAPDEG];         // uint4 row offsets (s * 64)
    __shared__ float s_inv[HH];
    __shared__ float s_acc[64][9];          // odd-half partials (pad 9)

    const float4 adst = *(const float4*)&g_adst[i * HH];

    for (int j = tid; j < deg; j += 128) {
        int s = g_src2[i * CAPDEG + j];
        s_off[j] = s * (HC / 8);
        float4 a = *(const float4*)&g_asrc[s * HH];
        float l0 = a.x + adst.x; l0 = (l0 > 0.f) ? l0 : 0.2f * l0;
        float l1 = a.y + adst.y; l1 = (l1 > 0.f) ? l1 : 0.2f * l1;
        float l2 = a.z + adst.z; l2 = (l2 > 0.f) ? l2 : 0.2f * l2;
        float l3 = a.w + adst.w; l3 = (l3 > 0.f) ? l3 : 0.2f * l3;
        s_e[0][j] = l0; s_e[1][j] = l1; s_e[2][j] = l2; s_e[3][j] = l3;
    }
    __syncthreads();
    if (tid == 0) g_cursor[i] = 0;   // restore invariant for next replay

    // softmax: warp wid owns head wid's slice
    float m = -INFINITY;
    for (int j = lane; j < deg; j += 32) m = fmaxf(m, s_e[wid][j]);
#pragma unroll
    for (int off = 16; off > 0; off >>= 1)
        m = fmaxf(m, __shfl_xor_sync(0xFFFFFFFFu, m, off));

    float ssum = 0.f;
    for (int j = lane; j < deg; j += 32) {
        float e = __expf(s_e[wid][j] - m);
        s_e[wid][j] = e;
        ssum += e;
    }
#pragma unroll
    for (int off = 16; off > 0; off >>= 1)
        ssum += __shfl_xor_sync(0xFFFFFFFFu, ssum, off);
    if (lane == 0) s_inv[wid] = 1.f / (ssum + 1e-16f);
    __syncthreads();   // gather reads other warps' s_e slices + s_inv

    // gather: 2 edges in flight, one uint4 (8 fp16 channels) per thread
    const uint4* __restrict__ hrow = (const uint4*)g_h2;  // 64 uint4 per node
    float acc[8];
#pragma unroll
    for (int c = 0; c < 8; c++) acc[c] = 0.f;
#pragma unroll 4
    for (int k = half; k < deg; k += 2) {
        float a = s_e[chead][k];
        uint4 u = hrow[s_off[k] + sub];
        float2 f0 = __half22float2(*(__half2*)&u.x);
        float2 f1 = __half22float2(*(__half2*)&u.y);
        float2 f2 = __half22float2(*(__half2*)&u.z);
        float2 f3 = __half22float2(*(__half2*)&u.w);
        acc[0] += a * f0.x; acc[1] += a * f0.y;
        acc[2] += a * f1.x; acc[3] += a * f1.y;
        acc[4] += a * f2.x; acc[5] += a * f2.y;
        acc[6] += a * f3.x; acc[7] += a * f3.y;
    }

    // combine the two edge-parity partials
    if (half == 1) {
#pragma unroll
        for (int c = 0; c < 8; c++) s_acc[sub][c] = acc[c];
    }
    __syncthreads();
    if (half == 0) {
        const float inv = s_inv[chead];
        const float4 b0 = *(const float4*)&bias[sub * 8];
        const float4 b1 = *(const float4*)&bias[sub * 8 + 4];
        float4 o0, o1;
        o0.x = (acc[0] + s_acc[sub][0]) * inv + b0.x;
        o0.y = (acc[1] + s_acc[sub][1]) * inv + b0.y;
        o0.z = (acc[2] + s_acc[sub][2]) * inv + b0.z;
        o0.w = (acc[3] + s_acc[sub][3]) * inv + b0.w;
        o1.x = (acc[4] + s_acc[sub][4]) * inv + b1.x;
        o1.y = (acc[5] + s_acc[sub][5]) * inv + b1.y;
        o1.z = (acc[6] + s_acc[sub][6]) * inv + b1.z;
        o1.w = (acc[7] + s_acc[sub][7]) * inv + b1.w;
        *(float4*)&out[(size_t)i * HC + sub * 8]     = o0;
        *(float4*)&out[(size_t)i * HC + sub * 8 + 4] = o1;
    }
}

// ---------------- launch -------------------------------------------------------
// main: cvtW -> hmma gemm (x converted inline) -> [wait fill] agg
// s1:   [wait fork] fill  (joins main before agg)
extern "C" void kernel_launch(void* const* d_in, const int* in_sizes, int n_in,
                              void* d_out, int out_size) {
    const float* x       = (const float*)d_in[0];
    const float* W       = (const float*)d_in[1];
    const float* att_src = (const float*)d_in[2];
    const float* att_dst = (const float*)d_in[3];
    const float* bias    = (const float*)d_in[4];
    const void*  edge    = d_in[5];
    float*       out     = (float*)d_out;

    static cudaStream_t s1 = nullptr;
    static cudaEvent_t  ev_fork = nullptr, ev_csr = nullptr;
    if (s1 == nullptr) {
        cudaStreamCreateWithFlags(&s1, cudaStreamNonBlocking);
        cudaEventCreateWithFlags(&ev_fork, cudaEventDisableTiming);
        cudaEventCreateWithFlags(&ev_csr, cudaEventDisableTiming);
    }

    // fork the bucket-CSR build onto s1
    cudaEventRecord(ev_fork, 0);
    cudaStreamWaitEvent(s1, ev_fork, 0);
    fill_kernel<<<(ET + 256 * EB - 1) / (256 * EB), 256, 0, s1>>>(edge);
    cudaEventRecord(ev_csr, s1);

    // W^T convert + tensor-core gemm on the main stream
    cvtw_kernel<<<(HC * CC + 255) / 256, 256>>>(W);
    gemm_kernel<<<dim3((NN + 127) / 128, HH), 256>>>(x, att_src, att_dst);

    // join, then fused softmax+gather
    cudaStreamWaitEvent(0, ev_csr, 0);
    agg_kernel<<<NN, 128>>>(bias, out);
}

// round 14
// speedup vs baseline: 1.0426x; 1.0426x over previous
#include <cuda_runtime.h>
#include <cuda_fp16.h>
#include <math.h>

// Problem constants (fixed by the dataset)
#define NN     10000         // nodes
#define EE     320000        // edges (before self loops)
#define ET     (EE + NN)     // edges incl. self loops
#define HH     4             // heads
#define CC     128           // channels per head
#define HC     (HH * CC)     // 512
#define EB     4             // edges per thread in fill
#define CAPDEG 192           // per-node bucket capacity (Poisson(33); P(>80)~1e-12)
#define PADK   136           // smem row stride (halfs) for conflict-free ldmatrix

// ---------------- scratch (static device globals; no allocs allowed) ----------
__device__ __align__(16) __half2 g_h2[NN * HC / 2];   // fp16 feats [N, H*C] (10.2 MB)
__device__ __align__(16) __half  g_wt[HC * CC];       // fp16 W^T [512,128] (128 KB)
__device__ float g_asrc[NN * HH];        // per-node src attention logits [N,4]
__device__ float g_adst[NN * HH];        // per-node dst attention logits [N,4]
__device__ int   g_cursor[NN];           // bucket cursors (zero at entry; agg restores)
__device__ int   g_src2[NN * CAPDEG];    // bucketed edge sources [node][CAPDEG]

// ---------------- inline edge-dtype detection ---------------------------------
__device__ __forceinline__ int detect_is64(const int* __restrict__ e32) {
    int any = 0;
#pragma unroll
    for (int k = 0; k < 8; k++) any |= e32[2 * k + 1];
    return any == 0;
}
__device__ __forceinline__ int edge_at(const void* edge, long long idx, int is64) {
    if (is64) return (int)((const long long*)edge)[idx];
    return ((const int*)edge)[idx];
}
__device__ __forceinline__ unsigned smem_u32(const void* p) {
    return (unsigned)__cvta_generic_to_shared(p);
}

// ---------------- cvt: W -> W^T fp16 (tiny) ------------------------------------
__global__ void cvtw_kernel(const float* __restrict__ W) {
    int j = blockIdx.x * blockDim.x + threadIdx.x;
    if (j < HC * CC) {                 // W^T[n][k] = W[k][n]
        int n = j >> 7, k = j & 127;
        g_wt[j] = __float2half(W[k * HC + n]);
    }
}

// ---------------- HMMA GEMM + fused attention dots -----------------------------
// h[N,512] = x[N,128] @ W[128,512] in fp16 tensor cores, fp32 accumulate.
// Block: 128 rows x 128 cols (one head). 8 warps as 4x2, each warp 32x64.
// Full K staged in one shot (dynamic smem, 69.6 KB): ONE sync, then 8 kk steps.
__global__ void __launch_bounds__(256) gemm_kernel(
        const float* __restrict__ x,
        const float* __restrict__ att_src, const float* __restrict__ att_dst) {
    extern __shared__ __half smh[];
    __half* sA = smh;                      // [128][PADK]
    __half* sB = smh + 128 * PADK;         // [128][PADK]
    __shared__ float sdot[128][4];

    const int tid  = threadIdx.x;
    const int wid  = tid >> 5;
    const int lane = tid & 31;
    const int wm   = wid & 3;          // row group: wm*32
    const int wn   = wid >> 2;         // col group: wn*64
    const int row0 = blockIdx.x * 128;
    const int head = blockIdx.y;

    // stage A (x fp32 -> fp16 inline) and B (W^T fp16): 2048 8-half chunks each
#pragma unroll
    for (int cc = 0; cc < 8; cc++) {
        int ch = tid + cc * 256;           // 0..2047
        int r = ch >> 4, k8 = ch & 15;
        int rg = row0 + r;
        union alignas(16) { __half2 h2[4]; uint4 u; } v;
        if (rg < NN) {
            const float4 f0 = *(const float4*)&x[rg * CC + k8 * 8];
            const float4 f1 = *(const float4*)&x[rg * CC + k8 * 8 + 4];
            v.h2[0] = __floats2half2_rn(f0.x, f0.y);
            v.h2[1] = __floats2half2_rn(f0.z, f0.w);
            v.h2[2] = __floats2half2_rn(f1.x, f1.y);
            v.h2[3] = __floats2half2_rn(f1.z, f1.w);
        } else {
            v.u = make_uint4(0, 0, 0, 0);
        }
        *(uint4*)&sA[r * PADK + k8 * 8] = v.u;
        uint4 w = *(const uint4*)&g_wt[(head * 128 + r) * CC + k8 * 8];
        *(uint4*)&sB[r * PADK + k8 * 8] = w;
    }
    __syncthreads();                       // the only mainloop sync

    float c[2][8][4];
#pragma unroll
    for (int mt = 0; mt < 2; mt++)
#pragma unroll
        for (int nt = 0; nt < 8; nt++)
#pragma unroll
            for (int q = 0; q < 4; q++) c[mt][nt][q] = 0.f;

#pragma unroll
    for (int kk = 0; kk < 8; kk++) {
        const int k = kk * 16;
        unsigned a[2][4], b[8][2];
#pragma unroll
        for (int mt = 0; mt < 2; mt++) {
            int am = wm * 32 + mt * 16;
            unsigned addr = smem_u32(&sA[(am + (lane & 15)) * PADK + k + ((lane >> 4) << 3)]);
            asm volatile("ldmatrix.sync.aligned.m8n8.x4.shared.b16 {%0,%1,%2,%3}, [%4];"
                         : "=r"(a[mt][0]), "=r"(a[mt][1]), "=r"(a[mt][2]), "=r"(a[mt][3])
                         : "r"(addr));
        }
#pragma unroll
        for (int nt = 0; nt < 8; nt++) {
            int bn = wn * 64 + nt * 8;
            int l = lane & 15;
            unsigned addr = smem_u32(&sB[(bn + (l & 7)) * PADK + k + ((l >> 3) << 3)]);
            asm volatile("ldmatrix.sync.aligned.m8n8.x2.shared.b16 {%0,%1}, [%2];"
                         : "=r"(b[nt][0]), "=r"(b[nt][1]) : "r"(addr));
        }
#pragma unroll
        for (int mt = 0; mt < 2; mt++)
#pragma unroll
            for (int nt = 0; nt < 8; nt++) {
                asm volatile(
                    "mma.sync.aligned.m16n8k16.row.col.f32.f16.f16.f32 "
                    "{%0,%1,%2,%3}, {%4,%5,%6,%7}, {%8,%9}, {%0,%1,%2,%3};"
                    : "+f"(c[mt][nt][0]), "+f"(c[mt][nt][1]),
                      "+f"(c[mt][nt][2]), "+f"(c[mt][nt][3])
                    : "r"(a[mt][0]), "r"(a[mt][1]), "r"(a[mt][2]), "r"(a[mt][3]),
                      "r"(b[nt][0]), "r"(b[nt][1]));
            }
    }

    // epilogue: h (fp16) stores + attention dot partials
    const int q = lane & 3;            // col pair selector
    const int rq = lane >> 2;          // row within m8
    float vs1[2] = {0.f, 0.f}, vs2[2] = {0.f, 0.f};
    float vd1[2] = {0.f, 0.f}, vd2[2] = {0.f, 0.f};
#pragma unroll
    for (int nt = 0; nt < 8; nt++) {
        int col = wn * 64 + nt * 8 + q * 2;        // within-head col
        float as0 = att_src[head * CC + col], as1 = att_src[head * CC + col + 1];
        float ad0 = att_dst[head * CC + col], ad1 = att_dst[head * CC + col + 1];
#pragma unroll
        for (int mt = 0; mt < 2; mt++) {
            int r1 = row0 + wm * 32 + mt * 16 + rq;
            int r2 = r1 + 8;
            if (r1 < NN)
                g_h2[(size_t)r1 * (HC / 2) + (head * CC + col) / 2] =
                    __floats2half2_rn(c[mt][nt][0], c[mt][nt][1]);
            if (r2 < NN)
                g_h2[(size_t)r2 * (HC / 2) + (head * CC + col) / 2] =
                    __floats2half2_rn(c[mt][nt][2], c[mt][nt][3]);
            vs1[mt] += c[mt][nt][0] * as0 + c[mt][nt][1] * as1;
            vs2[mt] += c[mt][nt][2] * as0 + c[mt][nt][3] * as1;
            vd1[mt] += c[mt][nt][0] * ad0 + c[mt][nt][1] * ad1;
            vd2[mt] += c[mt][nt][2] * ad0 + c[mt][nt][3] * ad1;
        }
    }
#pragma unroll
    for (int mt = 0; mt < 2; mt++) {
#pragma unroll
        for (int off = 1; off <= 2; off <<= 1) {
            vs1[mt] += __shfl_xor_sync(0xFFFFFFFFu, vs1[mt], off);
            vs2[mt] += __shfl_xor_sync(0xFFFFFFFFu, vs2[mt], off);
            vd1[mt] += __shfl_xor_sync(0xFFFFFFFFu, vd1[mt], off);
            vd2[mt] += __shfl_xor_sync(0xFFFFFFFFu, vd2[mt], off);
        }
        if (q == 0) {
            int rl = wm * 32 + mt * 16 + rq;
            sdot[rl][wn] = vs1[mt];     sdot[rl][2 + wn] = vd1[mt];
            sdot[rl + 8][wn] = vs2[mt]; sdot[rl + 8][2 + wn] = vd2[mt];
        }
    }
    __syncthreads();
    if (tid < 128) {
        int rg = row0 + tid;
        if (rg < NN) {
            g_asrc[rg * HH + head] = sdot[tid][0] + sdot[tid][1];
            g_adst[rg * HH + head] = sdot[tid][2] + sdot[tid][3];
        }
    }
}

// ---------------- bucket fill: edges + self loops ------------------------------
__global__ void fill_kernel(const void* __restrict__ edge) {
    int e0 = (blockIdx.x * blockDim.x + threadIdx.x) * EB;
    if (e0 >= ET) return;
    int is64 = detect_is64((const int*)edge);
    int s[EB], d[EB];
#pragma unroll
    for (int q = 0; q < EB; q++) {
        int e = e0 + q;
        s[q] = -1; d[q] = -1;
        if (e < ET) {
            if (e < EE) {
                s[q] = edge_at(edge, (long long)e, is64);
                d[q] = edge_at(edge, (long long)EE + e, is64);
            } else {
                s[q] = e - EE; d[q] = e - EE;
            }
        }
    }
#pragma unroll
    for (int q = 0; q < EB; q++) {
        if ((unsigned)d[q] >= NN || (unsigned)s[q] >= NN) continue;
        int pos = atomicAdd(&g_cursor[d[q]], 1);
        if (pos < CAPDEG) g_src2[d[q] * CAPDEG + pos] = s[q];
    }
}

// ---------------- fused softmax + gather aggregation (R12 measured-best) -------
// Block = 128 threads = one node; warp h = head h; thread t owns 4 channels.
// Reads its own cursor as degree and resets it (next replay's fill invariant).
__global__ void __launch_bounds__(128) agg_kernel(
        const float* __restrict__ bias, float* __restrict__ out) {
    const int i    = blockIdx.x;
    const int tid  = threadIdx.x;
    const int head = tid >> 5;
    const int lane = tid & 31;
    const int deg  = min(g_cursor[i], CAPDEG);

    __shared__ float s_e[HH][CAPDEG];
    __shared__ int   s_src[CAPDEG];

    const float4 adst = *(const float4*)&g_adst[i * HH];

    for (int j = tid; j < deg; j += 128) {
        int s = g_src2[i * CAPDEG + j];
        s_src[j] = s;
        float4 a = *(const float4*)&g_asrc[s * HH];
        float l0 = a.x + adst.x; l0 = (l0 > 0.f) ? l0 : 0.2f * l0;
        float l1 = a.y + adst.y; l1 = (l1 > 0.f) ? l1 : 0.2f * l1;
        float l2 = a.z + adst.z; l2 = (l2 > 0.f) ? l2 : 0.2f * l2;
        float l3 = a.w + adst.w; l3 = (l3 > 0.f) ? l3 : 0.2f * l3;
        s_e[0][j] = l0; s_e[1][j] = l1; s_e[2][j] = l2; s_e[3][j] = l3;
    }
    __syncthreads();   // all threads have read cursor + filled logits
    if (tid == 0) g_cursor[i] = 0;   // restore invariant for next replay

    float m = -INFINITY;
    for (int j = lane; j < deg; j += 32) m = fmaxf(m, s_e[head][j]);
#pragma unroll
    for (int off = 16; off > 0; off >>= 1)
        m = fmaxf(m, __shfl_xor_sync(0xFFFFFFFFu, m, off));

    float ssum = 0.f;
    for (int j = lane; j < deg; j += 32) {
        float e = __expf(s_e[head][j] - m);
        s_e[head][j] = e;
        ssum += e;
    }
#pragma unroll
    for (int off = 16; off > 0; off >>= 1)
        ssum += __shfl_xor_sync(0xFFFFFFFFu, ssum, off);
    const float inv = 1.f / (ssum + 1e-16f);
    __syncwarp();

    const uint2* __restrict__ hrow = (const uint2*)g_h2;  // 128 uint2 per node
    float4 acc = make_float4(0.f, 0.f, 0.f, 0.f);
#pragma unroll 4
    for (int k = 0; k < deg; k++) {
        int   s = s_src[k];
        float a = s_e[head][k];
        uint2 u = hrow[s * (HC / 4) + tid];
        float2 f0 = __half22float2(*(__half2*)&u.x);
        float2 f1 = __half22float2(*(__half2*)&u.y);
        acc.x += a * f0.x;
        acc.y += a * f0.y;
        acc.z += a * f1.x;
        acc.w += a * f1.y;
    }

    const float4 b = *(const float4*)&bias[tid * 4];
    float4 o;
    o.x = acc.x * inv + b.x;
    o.y = acc.y * inv + b.y;
    o.z = acc.z * inv + b.z;
    o.w = acc.w * inv + b.w;
    *(float4*)&out[(size_t)i * HC + tid * 4] = o;
}

// ---------------- launch -------------------------------------------------------
// main: cvtW -> hmma gemm (full-K single-stage) -> [wait fill] agg
// s1:   [wait fork] fill  (joins main before agg)
extern "C" void kernel_launch(void* const* d_in, const int* in_sizes, int n_in,
                              void* d_out, int out_size) {
    const float* x       = (const float*)d_in[0];
    const float* W       = (const float*)d_in[1];
    const float* att_src = (const float*)d_in[2];
    const float* att_dst = (const float*)d_in[3];
    const float* bias    = (const float*)d_in[4];
    const void*  edge    = d_in[5];
    float*       out     = (float*)d_out;

    const int GEMM_SMEM = 2 * 128 * PADK * (int)sizeof(__half);  // 69,632 B

    static cudaStream_t s1 = nullptr;
    static cudaEvent_t  ev_fork = nullptr, ev_csr = nullptr;
    if (s1 == nullptr) {
        cudaStreamCreateWithFlags(&s1, cudaStreamNonBlocking);
        cudaEventCreateWithFlags(&ev_fork, cudaEventDisableTiming);
        cudaEventCreateWithFlags(&ev_csr, cudaEventDisableTiming);
        cudaFuncSetAttribute(gemm_kernel,
                             cudaFuncAttributeMaxDynamicSharedMemorySize, GEMM_SMEM);
    }

    // fork the bucket-CSR build onto s1
    cudaEventRecord(ev_fork, 0);
    cudaStreamWaitEvent(s1, ev_fork, 0);
    fill_kernel<<<(ET + 256 * EB - 1) / (256 * EB), 256, 0, s1>>>(edge);
    cudaEventRecord(ev_csr, s1);

    // W^T convert + tensor-core gemm on the main stream
    cvtw_kernel<<<(HC * CC + 255) / 256, 256>>>(W);
    gemm_kernel<<<dim3((NN + 127) / 128, HH), 256, GEMM_SMEM>>>(x, att_src, att_dst);

    // join, then fused softmax+gather
    cudaStreamWaitEvent(0, ev_csr, 0);
    agg_kernel<<<NN, 128>>>(bias, out);
}

// round 15
// speedup vs baseline: 1.1589x; 1.1115x over previous
#include <cuda_runtime.h>
#include <cuda_fp16.h>
#include <math.h>

// Problem constants (fixed by the dataset)
#define NN     10000         // nodes
#define EE     320000        // edges (before self loops)
#define ET     (EE + NN)     // edges incl. self loops
#define HH     4             // heads
#define CC     128           // channels per head
#define HC     (HH * CC)     // 512
#define EB     4             // edges per thread in fill
#define CAPDEG 192           // per-node bucket capacity (Poisson(33); P(>80)~1e-12)
#define PADK   136           // smem row stride (halfs), conflict-free ldmatrix

#define GEMM_MTILES ((NN + 127) / 128)       // 79
#define GEMM_BLOCKS (GEMM_MTILES * HH)       // 316
#define FILL_BLOCKS ((ET + 256 * EB - 1) / (256 * EB))  // 323

// ---------------- scratch (static device globals; no allocs allowed) ----------
__device__ __align__(16) __half2 g_h2[NN * HC / 2];   // fp16 feats [N, H*C] (10.2 MB)
__device__ float g_asrc[NN * HH];        // per-node src attention logits [N,4]
__device__ float g_adst[NN * HH];        // per-node dst attention logits [N,4]
__device__ int   g_cursor[NN];           // bucket cursors (zero at entry; agg restores)
__device__ int   g_src2[NN * CAPDEG];    // bucketed edge sources [node][CAPDEG]

// ---------------- inline edge-dtype detection ---------------------------------
__device__ __forceinline__ int detect_is64(const int* __restrict__ e32) {
    int any = 0;
#pragma unroll
    for (int k = 0; k < 8; k++) any |= e32[2 * k + 1];
    return any == 0;
}
__device__ __forceinline__ int edge_at(const void* edge, long long idx, int is64) {
    if (is64) return (int)((const long long*)edge)[idx];
    return ((const int*)edge)[idx];
}
__device__ __forceinline__ unsigned smem_u32(const void* p) {
    return (unsigned)__cvta_generic_to_shared(p);
}

// ---------------- fused prep: HMMA GEMM tiles + edge-bucket fill ---------------
// blockIdx.x <  GEMM_BLOCKS: one 128x128 output tile (head = bid&3) of
//   h = x @ W with fp16 tensor cores; x AND W converted fp32->fp16 inline.
//   B stored row-major [k][n]; B fragments via ldmatrix.trans.
// blockIdx.x >= GEMM_BLOCKS: fill 1024 edges into the destination buckets.
__global__ void __launch_bounds__(256) prep_kernel(
        const float* __restrict__ x, const float* __restrict__ W,
        const float* __restrict__ att_src, const float* __restrict__ att_dst,
        const void* __restrict__ edge) {
    const int bid = blockIdx.x;
    const int tid = threadIdx.x;

    if (bid >= GEMM_BLOCKS) {
        // ---------------- fill path ----------------
        int e0 = ((bid - GEMM_BLOCKS) * 256 + tid) * EB;
        if (e0 >= ET) return;
        int is64 = detect_is64((const int*)edge);
        int s[EB], d[EB];
#pragma unroll
        for (int q = 0; q < EB; q++) {
            int e = e0 + q;
            s[q] = -1; d[q] = -1;
            if (e < ET) {
                if (e < EE) {
                    s[q] = edge_at(edge, (long long)e, is64);
                    d[q] = edge_at(edge, (long long)EE + e, is64);
                } else {
                    s[q] = e - EE; d[q] = e - EE;
                }
            }
        }
#pragma unroll
        for (int q = 0; q < EB; q++) {
            if ((unsigned)d[q] >= NN || (unsigned)s[q] >= NN) continue;
            int pos = atomicAdd(&g_cursor[d[q]], 1);
            if (pos < CAPDEG) g_src2[d[q] * CAPDEG + pos] = s[q];
        }
        return;
    }

    // ---------------- gemm path ----------------
    extern __shared__ __half smh[];
    __half* sA = smh;                      // [128][PADK]  rows = m, k contiguous
    __half* sB = smh + 128 * PADK;         // [128][PADK]  rows = k, n contiguous
    __shared__ float sdot[128][4];

    const int wid  = tid >> 5;
    const int lane = tid & 31;
    const int wm   = wid & 3;          // row group: wm*32
    const int wn   = wid >> 2;         // col group: wn*64
    const int head = bid & 3;
    const int row0 = (bid >> 2) * 128;

    // stage A (x fp32 -> fp16) and B (W fp32 -> fp16, natural [k][n] layout)
#pragma unroll
    for (int cc = 0; cc < 8; cc++) {
        int ch = tid + cc * 256;           // 0..2047 chunks of 8 halfs
        int r = ch >> 4, k8 = ch & 15;
        union alignas(16) { __half2 h2[4]; uint4 u; } v;
        // A: row r of x (m index), halfs k8*8..k8*8+7
        int rg = row0 + r;
        if (rg < NN) {
            const float4 f0 = *(const float4*)&x[rg * CC + k8 * 8];
            const float4 f1 = *(const float4*)&x[rg * CC + k8 * 8 + 4];
            v.h2[0] = __floats2half2_rn(f0.x, f0.y);
            v.h2[1] = __floats2half2_rn(f0.z, f0.w);
            v.h2[2] = __floats2half2_rn(f1.x, f1.y);
            v.h2[3] = __floats2half2_rn(f1.z, f1.w);
        } else {
            v.u = make_uint4(0, 0, 0, 0);
        }
        *(uint4*)&sA[r * PADK + k8 * 8] = v.u;
        // B: row r of W (k index), cols head*128 + k8*8 .. +7 (contiguous n)
        {
            const float4 f0 = *(const float4*)&W[r * HC + head * CC + k8 * 8];
            const float4 f1 = *(const float4*)&W[r * HC + head * CC + k8 * 8 + 4];
            union alignas(16) { __half2 h2[4]; uint4 u; } w;
            w.h2[0] = __floats2half2_rn(f0.x, f0.y);
            w.h2[1] = __floats2half2_rn(f0.z, f0.w);
            w.h2[2] = __floats2half2_rn(f1.x, f1.y);
            w.h2[3] = __floats2half2_rn(f1.z, f1.w);
            *(uint4*)&sB[r * PADK + k8 * 8] = w.u;
        }
    }
    __syncthreads();                       // the only mainloop sync

    float c[2][8][4];
#pragma unroll
    for (int mt = 0; mt < 2; mt++)
#pragma unroll
        for (int nt = 0; nt < 8; nt++)
#pragma unroll
            for (int q = 0; q < 4; q++) c[mt][nt][q] = 0.f;

#pragma unroll
    for (int kk = 0; kk < 8; kk++) {
        const int k = kk * 16;
        unsigned a[2][4], b[8][2];
#pragma unroll
        for (int mt = 0; mt < 2; mt++) {
            int am = wm * 32 + mt * 16;
            unsigned addr = smem_u32(&sA[(am + (lane & 15)) * PADK + k + ((lane >> 4) << 3)]);
            asm volatile("ldmatrix.sync.aligned.m8n8.x4.shared.b16 {%0,%1,%2,%3}, [%4];"
                         : "=r"(a[mt][0]), "=r"(a[mt][1]), "=r"(a[mt][2]), "=r"(a[mt][3])
                         : "r"(addr));
        }
#pragma unroll
        for (int nt = 0; nt < 8; nt++) {
            int bn = wn * 64 + nt * 8;
            int l = lane & 15;
            // B row-major [k][n]: rows k..k+15 at column bn, transposed on load
            unsigned addr = smem_u32(&sB[(k + l) * PADK + bn]);
            asm volatile("ldmatrix.sync.aligned.m8n8.x2.trans.shared.b16 {%0,%1}, [%2];"
                         : "=r"(b[nt][0]), "=r"(b[nt][1]) : "r"(addr));
        }
#pragma unroll
        for (int mt = 0; mt < 2; mt++)
#pragma unroll
            for (int nt = 0; nt < 8; nt++) {
                asm volatile(
                    "mma.sync.aligned.m16n8k16.row.col.f32.f16.f16.f32 "
                    "{%0,%1,%2,%3}, {%4,%5,%6,%7}, {%8,%9}, {%0,%1,%2,%3};"
                    : "+f"(c[mt][nt][0]), "+f"(c[mt][nt][1]),
                      "+f"(c[mt][nt][2]), "+f"(c[mt][nt][3])
                    : "r"(a[mt][0]), "r"(a[mt][1]), "r"(a[mt][2]), "r"(a[mt][3]),
                      "r"(b[nt][0]), "r"(b[nt][1]));
            }
    }

    // epilogue: h (fp16) stores + attention dot partials
    const int q = lane & 3;            // col pair selector
    const int rq = lane >> 2;          // row within m8
    float vs1[2] = {0.f, 0.f}, vs2[2] = {0.f, 0.f};
    float vd1[2] = {0.f, 0.f}, vd2[2] = {0.f, 0.f};
#pragma unroll
    for (int nt = 0; nt < 8; nt++) {
        int col = wn * 64 + nt * 8 + q * 2;        // within-head col
        float as0 = att_src[head * CC + col], as1 = att_src[head * CC + col + 1];
        float ad0 = att_dst[head * CC + col], ad1 = att_dst[head * CC + col + 1];
#pragma unroll
        for (int mt = 0; mt < 2; mt++) {
            int r1 = row0 + wm * 32 + mt * 16 + rq;
            int r2 = r1 + 8;
            if (r1 < NN)
                g_h2[(size_t)r1 * (HC / 2) + (head * CC + col) / 2] =
                    __floats2half2_rn(c[mt][nt][0], c[mt][nt][1]);
            if (r2 < NN)
                g_h2[(size_t)r2 * (HC / 2) + (head * CC + col) / 2] =
                    __floats2half2_rn(c[mt][nt][2], c[mt][nt][3]);
            vs1[mt] += c[mt][nt][0] * as0 + c[mt][nt][1] * as1;
            vs2[mt] += c[mt][nt][2] * as0 + c[mt][nt][3] * as1;
            vd1[mt] += c[mt][nt][0] * ad0 + c[mt][nt][1] * ad1;
            vd2[mt] += c[mt][nt][2] * ad0 + c[mt][nt][3] * ad1;
        }
    }
#pragma unroll
    for (int mt = 0; mt < 2; mt++) {
#pragma unroll
        for (int off = 1; off <= 2; off <<= 1) {
            vs1[mt] += __shfl_xor_sync(0xFFFFFFFFu, vs1[mt], off);
            vs2[mt] += __shfl_xor_sync(0xFFFFFFFFu, vs2[mt], off);
            vd1[mt] += __shfl_xor_sync(0xFFFFFFFFu, vd1[mt], off);
            vd2[mt] += __shfl_xor_sync(0xFFFFFFFFu, vd2[mt], off);
        }
        if (q == 0) {
            int rl = wm * 32 + mt * 16 + rq;
            sdot[rl][wn] = vs1[mt];     sdot[rl][2 + wn] = vd1[mt];
            sdot[rl + 8][wn] = vs2[mt]; sdot[rl + 8][2 + wn] = vd2[mt];
        }
    }
    __syncthreads();
    if (tid < 128) {
        int rg = row0 + tid;
        if (rg < NN) {
            g_asrc[rg * HH + head] = sdot[tid][0] + sdot[tid][1];
            g_adst[rg * HH + head] = sdot[tid][2] + sdot[tid][3];
        }
    }
}

// ---------------- fused softmax + gather aggregation (measured-best form) ------
// Block = 128 threads = one node; warp h = head h; thread t owns 4 channels.
// Reads its own cursor as degree and resets it (next replay's fill invariant).
__global__ void __launch_bounds__(128) agg_kernel(
        const float* __restrict__ bias, float* __restrict__ out) {
    const int i    = blockIdx.x;
    const int tid  = threadIdx.x;
    const int head = tid >> 5;
    const int lane = tid & 31;
    const int deg  = min(g_cursor[i], CAPDEG);

    __shared__ float s_e[HH][CAPDEG];
    __shared__ int   s_src[CAPDEG];

    const float4 adst = *(const float4*)&g_adst[i * HH];

    for (int j = tid; j < deg; j += 128) {
        int s = g_src2[i * CAPDEG + j];
        s_src[j] = s;
        float4 a = *(const float4*)&g_asrc[s * HH];
        float l0 = a.x + adst.x; l0 = (l0 > 0.f) ? l0 : 0.2f * l0;
        float l1 = a.y + adst.y; l1 = (l1 > 0.f) ? l1 : 0.2f * l1;
        float l2 = a.z + adst.z; l2 = (l2 > 0.f) ? l2 : 0.2f * l2;
        float l3 = a.w + adst.w; l3 = (l3 > 0.f) ? l3 : 0.2f * l3;
        s_e[0][j] = l0; s_e[1][j] = l1; s_e[2][j] = l2; s_e[3][j] = l3;
    }
    __syncthreads();   // all threads have read cursor + filled logits
    if (tid == 0) g_cursor[i] = 0;   // restore invariant for next replay

    float m = -INFINITY;
    for (int j = lane; j < deg; j += 32) m = fmaxf(m, s_e[head][j]);
#pragma unroll
    for (int off = 16; off > 0; off >>= 1)
        m = fmaxf(m, __shfl_xor_sync(0xFFFFFFFFu, m, off));

    float ssum = 0.f;
    for (int j = lane; j < deg; j += 32) {
        float e = __expf(s_e[head][j] - m);
        s_e[head][j] = e;
        ssum += e;
    }
#pragma unroll
    for (int off = 16; off > 0; off >>= 1)
        ssum += __shfl_xor_sync(0xFFFFFFFFu, ssum, off);
    const float inv = 1.f / (ssum + 1e-16f);
    __syncwarp();

    const uint2* __restrict__ hrow = (const uint2*)g_h2;  // 128 uint2 per node
    float4 acc = make_float4(0.f, 0.f, 0.f, 0.f);
#pragma unroll 4
    for (int k = 0; k < deg; k++) {
        int   s = s_src[k];
        float a = s_e[head][k];
        uint2 u = hrow[s * (HC / 4) + tid];
        float2 f0 = __half22float2(*(__half2*)&u.x);
        float2 f1 = __half22float2(*(__half2*)&u.y);
        acc.x += a * f0.x;
        acc.y += a * f0.y;
        acc.z += a * f1.x;
        acc.w += a * f1.y;
    }

    const float4 b = *(const float4*)&bias[tid * 4];
    float4 o;
    o.x = acc.x * inv + b.x;
    o.y = acc.y * inv + b.y;
    o.z = acc.z * inv + b.z;
    o.w = acc.w * inv + b.w;
    *(float4*)&out[(size_t)i * HC + tid * 4] = o;
}

// ---------------- launch -------------------------------------------------------
// Two launches, one stream, no events:
//   prep (gemm tiles + fill blocks, heterogeneous grid)  ->  agg
extern "C" void kernel_launch(void* const* d_in, const int* in_sizes, int n_in,
                              void* d_out, int out_size) {
    const float* x       = (const float*)d_in[0];
    const float* W       = (const float*)d_in[1];
    const float* att_src = (const float*)d_in[2];
    const float* att_dst = (const float*)d_in[3];
    const float* bias    = (const float*)d_in[4];
    const void*  edge    = d_in[5];
    float*       out     = (float*)d_out;

    const int PREP_SMEM = 2 * 128 * PADK * (int)sizeof(__half);  // 69,632 B

    static bool inited = false;
    if (!inited) {
        cudaFuncSetAttribute(prep_kernel,
                             cudaFuncAttributeMaxDynamicSharedMemorySize, PREP_SMEM);
        inited = true;
    }

    prep_kernel<<<GEMM_BLOCKS + FILL_BLOCKS, 256, PREP_SMEM>>>(
        x, W, att_src, att_dst, edge);
    agg_kernel<<<NN, 128>>>(bias, out);
}